// round 14
// baseline (speedup 1.0000x reference)
#include <cuda_runtime.h>
#include <cuda_fp16.h>
#include <math.h>

#define Bb 2
#define Ss 128
#define Hh 768
#define Cc 5
#define NEGV (-1024.0f)
#define Mm (Bb*Ss)          // 256
#define NTOT (Hh + Cc*Hh)   // 4608
#define NROWS (Bb*Ss*Cc)    // 1280
#define OUTN (Bb*Ss*Cc*Ss)  // 163840

#define KG8 (Hh/8)          // 96 k8-groups (tf32)
#define MI  (Mm/16)         // 16
#define NI8 (NTOT/8)        // 576

#define SEG 8
#define HSEG (Hh/SEG)       // 96
#define JP2 (HSEG/2)        // 48 half2 per segment
#define HH2 (Hh/2)          // 384

__device__ __half g_hp_h[Mm*Hh];
__device__ __half g_ha_h[Mm*Cc*Hh];
__device__ float g_part[SEG*OUTN];
__device__ int   g_ngMode;
__device__ unsigned g_ctr;
__device__ unsigned long long g_lnum;
__device__ unsigned long long g_lden;
__device__ unsigned g_Af[KG8*MI*128];     // A tf32 fragments (196608)
__device__ unsigned g_Bf[KG8*NI8*64];     // B tf32 fragments (3538944)

__device__ __forceinline__ unsigned to_tf32(float x){
    unsigned r; asm("cvt.rna.tf32.f32 %0, %1;" : "=r"(r) : "f"(x)); return r;
}

// ---------------------------------------------------------------------------
// prep: coalesced loads, scattered tf32 fragment stores (m16n8k8 layout).
//   A: thread=(m,k): mi=m>>4, g=k>>3; reg=((m>>3)&1)|(((k>>2)&1)<<1);
//      lane=((m&7)<<2)|(k&3); w=((g*MI+mi)*32+lane)*4+reg
//   B: thread=(n,k): ni=n>>3, g=k>>3; reg=(k>>2)&1;
//      lane=((n&7)<<2)|(k&3); w=((g*NI8+ni)*32+lane)*2+reg
// LAST BLOCK does ng dtype detection.
// ---------------------------------------------------------------------------
#define AW2 (Mm*Hh)          // 196608
#define BW2 (NTOT*Hh)        // 3538944
#define FRAGTOT (AW2+BW2)    // 3735552 = 14592*256
#define PREP_BLOCKS (FRAGTOT/256 + 1)

__global__ __launch_bounds__(256) void k_prep(const float* __restrict__ X,
        const float* __restrict__ Wp, const float* __restrict__ Wa,
        const unsigned char* __restrict__ ng){
    if (blockIdx.x == PREP_BLOCKS-1){
        __shared__ int s_b1, s_f3;
        if (threadIdx.x == 0){ s_b1 = 0; s_f3 = 0; }
        __syncthreads();
        int b1 = 0, f3 = 0;
        for (int i = threadIdx.x; i < 16384; i += 256){
            unsigned char v = ng[i];
            int o = i & 3;
            if (o == 1 && v) b1 = 1;
            if (o == 3 && v == 0x3F) f3 = 1;
        }
        if (b1) s_b1 = 1;
        if (f3) s_f3 = 1;
        __syncthreads();
        if (threadIdx.x == 0) g_ngMode = s_b1 ? 0 : (s_f3 ? 2 : 1);
        return;
    }
    int idx = blockIdx.x*256 + threadIdx.x;
    if (idx < AW2){
        int m = idx / Hh, k = idx % Hh;
        float v = X[idx];
        int mi = m >> 4, g = k >> 3;
        int reg  = ((m >> 3) & 1) | (((k >> 2) & 1) << 1);
        int lane = ((m & 7) << 2) | (k & 3);
        g_Af[((g*MI + mi)*32 + lane)*4 + reg] = to_tf32(v);
    } else {
        int t = idx - AW2;
        int n = t / Hh, k = t % Hh;
        float v = (n < Hh) ? Wp[n*Hh + k] : Wa[(n-Hh)*Hh + k];
        int ni = n >> 3, g = k >> 3;
        int reg  = (k >> 2) & 1;
        int lane = ((n & 7) << 2) | (k & 3);
        g_Bf[((g*NI8 + ni)*32 + lane)*2 + reg] = to_tf32(v);
    }
}

// ---------------------------------------------------------------------------
// GEMM: mma m16n8k8 tf32 single-pass, double-buffered.
// CTA tile 64(M) x 64(N), 8 warps = 2(M) x 4(N), warp tile 32x16. grid (72,4).
// Epilogue stores f16 g_hp_h / g_ha_h.
// ---------------------------------------------------------------------------
__device__ __forceinline__ void mma_tf32(float& d0, float& d1, float& d2, float& d3,
        unsigned a0, unsigned a1, unsigned a2, unsigned a3,
        unsigned b0, unsigned b1){
    asm volatile("mma.sync.aligned.m16n8k8.row.col.f32.tf32.tf32.f32 "
        "{%0,%1,%2,%3}, {%4,%5,%6,%7}, {%8,%9}, {%0,%1,%2,%3};"
        : "+f"(d0), "+f"(d1), "+f"(d2), "+f"(d3)
        : "r"(a0), "r"(a1), "r"(a2), "r"(a3), "r"(b0), "r"(b1));
}

__global__ __launch_bounds__(256) void k_gemm(const float* __restrict__ bp,
                                              const float* __restrict__ ba){
    int tid = threadIdx.x;
    int wid = tid >> 5, lane = tid & 31;
    int wr = wid >> 2, wc = wid & 3;
    int mi0 = blockIdx.y*4 + wr*2;
    int ni0 = blockIdx.x*8 + wc*2;

    float acc[2][2][4];
    #pragma unroll
    for (int i=0;i<2;i++) for (int j=0;j<2;j++) for (int q=0;q<4;q++) acc[i][j][q]=0.f;

    const uint4* pA = reinterpret_cast<const uint4*>(g_Af);
    const uint2* pB = reinterpret_cast<const uint2*>(g_Bf);

    uint4 Ac[2]; uint2 Bc[2];
    #pragma unroll
    for (int mf=0; mf<2; mf++) Ac[mf] = pA[(0*MI + mi0+mf)*32 + lane];
    #pragma unroll
    for (int nf=0; nf<2; nf++) Bc[nf] = pB[(0*NI8 + ni0+nf)*32 + lane];

    for (int g = 0; g < KG8; g++){
        uint4 An[2]; uint2 Bn[2];
        if (g+1 < KG8){
            #pragma unroll
            for (int mf=0; mf<2; mf++) An[mf] = pA[((g+1)*MI + mi0+mf)*32 + lane];
            #pragma unroll
            for (int nf=0; nf<2; nf++) Bn[nf] = pB[((g+1)*NI8 + ni0+nf)*32 + lane];
        }
        #pragma unroll
        for (int mf=0; mf<2; mf++)
            #pragma unroll
            for (int nf=0; nf<2; nf++)
                mma_tf32(acc[mf][nf][0], acc[mf][nf][1], acc[mf][nf][2], acc[mf][nf][3],
                         Ac[mf].x, Ac[mf].y, Ac[mf].z, Ac[mf].w, Bc[nf].x, Bc[nf].y);
        if (g+1 < KG8){
            #pragma unroll
            for (int mf=0; mf<2; mf++) Ac[mf] = An[mf];
            #pragma unroll
            for (int nf=0; nf<2; nf++) Bc[nf] = Bn[nf];
        }
    }

    int r = lane >> 2, c2 = (lane & 3)*2;
    #pragma unroll
    for (int nf=0; nf<2; nf++){
        int n = (ni0+nf)*8 + c2;
        float2 bias = (n < Hh) ? *(const float2*)&bp[n] : *(const float2*)&ba[n-Hh];
        #pragma unroll
        for (int mf=0; mf<2; mf++){
            int m1 = (mi0+mf)*16 + r;
            int m2 = m1 + 8;
            __half2 v1 = __floats2half2_rn(acc[mf][nf][0] + bias.x, acc[mf][nf][1] + bias.y);
            __half2 v2 = __floats2half2_rn(acc[mf][nf][2] + bias.x, acc[mf][nf][3] + bias.y);
            if (n < Hh){
                *(__half2*)&g_hp_h[m1*Hh + n] = v1;
                *(__half2*)&g_hp_h[m2*Hh + n] = v2;
            } else {
                *(__half2*)&g_ha_h[m1*(Cc*Hh) + (n-Hh)] = v1;
                *(__half2*)&g_ha_h[m2*(Cc*Hh) + (n-Hh)] = v2;
            }
        }
    }
}

// ---------------------------------------------------------------------------
// biaffine partial (unchanged, proven): all-f16x2, 8-way h-split,
// tile 32p x 8a, 128 threads, padded s_ha. grid 1024.
// ---------------------------------------------------------------------------
__global__ __launch_bounds__(128,8) void k_biaffine(const float* __restrict__ Wout){
    __shared__ __half2 s_hp[32][JP2+1];
    __shared__ __half2 s_ha[Cc][JP2][9];
    __shared__ __half2 s_w[Cc][JP2];
    int bx = blockIdx.x;
    int seg  = bx & 7;
    int rest = bx >> 3;
    int b   = rest >> 6;
    int rem = rest & 63;
    int p0 = (rem >> 4) * 32;
    int a0 = (rem & 15) * 8;
    int tid = threadIdx.x;
    int p = tid >> 3, a = tid & 7;
    int jbase = seg * JP2;

    const __half2* HP = reinterpret_cast<const __half2*>(g_hp_h);
    const __half2* HA = reinterpret_cast<const __half2*>(g_ha_h);

    #pragma unroll
    for (int i = 0; i < 12; i++){
        int idx = tid + i*128;
        int r = idx / JP2, jp = idx % JP2;
        s_hp[r][jp] = HP[(b*Ss + p0 + r)*HH2 + jbase + jp];
    }
    #pragma unroll
    for (int i = 0; i < 15; i++){
        int idx = tid + i*128;
        int al = idx / (Cc*JP2);
        int rr = idx % (Cc*JP2);
        int c = rr / JP2, jp = rr % JP2;
        s_ha[c][jp][al] = HA[((b*Ss + a0 + al)*Cc + c)*HH2 + jbase + jp];
    }
    for (int idx = tid; idx < Cc*JP2; idx += 128){
        int c = idx / JP2, jp = idx % JP2;
        float2 v = *(const float2*)&Wout[c*Hh + seg*HSEG + 2*jp];
        s_w[c][jp] = __floats2half2_rn(v.x, v.y);
    }
    __syncthreads();

    float fA[Cc] = {}, fB[Cc] = {};
    #pragma unroll 1
    for (int blk = 0; blk < 4; blk++){
        __half2 accA[Cc], accB[Cc];
        #pragma unroll
        for (int c=0;c<Cc;c++){
            accA[c] = __floats2half2_rn(0.f, 0.f);
            accB[c] = __floats2half2_rn(0.f, 0.f);
        }
        #pragma unroll
        for (int j=0;j<12;j++){
            int jp = blk*12 + j;
            __half2 hpA = s_hp[p][jp];
            __half2 hpB = s_hp[p+16][jp];
            #pragma unroll
            for (int c=0;c<Cc;c++){
                __half2 ha = s_ha[c][jp][a];
                __half2 w  = s_w[c][jp];
                __half2 xA = __hadd2(hpA, ha);
                __half2 xB = __hadd2(hpB, ha);
                unsigned tA, tB;
                asm("tanh.approx.f16x2 %0, %1;" : "=r"(tA) : "r"(*(unsigned*)&xA));
                asm("tanh.approx.f16x2 %0, %1;" : "=r"(tB) : "r"(*(unsigned*)&xB));
                accA[c] = __hfma2(*(__half2*)&tA, w, accA[c]);
                accB[c] = __hfma2(*(__half2*)&tB, w, accB[c]);
            }
        }
        #pragma unroll
        for (int c=0;c<Cc;c++){
            float2 vA = __half22float2(accA[c]);
            float2 vB = __half22float2(accB[c]);
            fA[c] += vA.x + vA.y;
            fB[c] += vB.x + vB.y;
        }
    }
    int pgA = p0 + p, pgB = p0 + p + 16, ag = a0 + a;
    #pragma unroll
    for (int c=0;c<Cc;c++){
        g_part[seg*OUTN + ((b*Ss+pgA)*Cc + c)*Ss + ag] = fA[c];
        g_part[seg*OUTN + ((b*Ss+pgB)*Cc + c)*Ss + ag] = fB[c];
    }
}

// ---------------------------------------------------------------------------
// combine (unchanged): warp-per-row, vectorized, int64 fixed-point loss.
// ---------------------------------------------------------------------------
#define CBLK (NROWS/4)   // 320
#define FPSCALE 4294967296.0

__global__ __launch_bounds__(128) void k_combine(const float* __restrict__ targ,
        const int* __restrict__ att, const void* __restrict__ ng,
        float* __restrict__ dst, float* __restrict__ out,
        int writeOut, int dstAligned, int writeLoss){
    const unsigned FULL = 0xffffffffu;
    int tid = threadIdx.x;
    int w = tid >> 5, lane = tid & 31;
    int row = blockIdx.x*4 + w;
    int bp = row / Cc;
    int b = bp >> 7;
    int base = row*Ss + lane*4;

    float4 v = make_float4(0.f,0.f,0.f,0.f);
    #pragma unroll
    for (int k=0;k<SEG;k++){
        float4 t = *(const float4*)&g_part[k*OUTN + base];
        v.x += t.x; v.y += t.y; v.z += t.z; v.w += t.w;
    }

    int mode = g_ngMode;
    bool m0=false, m1=false, m2=false, m3=false;
    if (mode == 1){
        #pragma unroll
        for (int c=0;c<Cc;c++){
            int4 q = *(const int4*)&((const int*)ng)[(bp*Cc + c)*Ss + lane*4];
            m0 |= q.x!=0; m1 |= q.y!=0; m2 |= q.z!=0; m3 |= q.w!=0;
        }
    } else if (mode == 2){
        #pragma unroll
        for (int c=0;c<Cc;c++){
            float4 q = *(const float4*)&((const float*)ng)[(bp*Cc + c)*Ss + lane*4];
            m0 |= q.x!=0.f; m1 |= q.y!=0.f; m2 |= q.z!=0.f; m3 |= q.w!=0.f;
        }
    } else {
        #pragma unroll
        for (int c=0;c<Cc;c++){
            uchar4 q = *(const uchar4*)&((const unsigned char*)ng)[(bp*Cc + c)*Ss + lane*4];
            m0 |= q.x!=0; m1 |= q.y!=0; m2 |= q.z!=0; m3 |= q.w!=0;
        }
    }
    int4 av = *(const int4*)&att[b*Ss + lane*4];
    v.x += (m0 && av.x>0) ? 0.f : NEGV;
    v.y += (m1 && av.y>0) ? 0.f : NEGV;
    v.z += (m2 && av.z>0) ? 0.f : NEGV;
    v.w += (m3 && av.w>0) ? 0.f : NEGV;
    if (writeOut){
        if (dstAligned){
            *(float4*)&dst[base] = v;
        } else {
            dst[base+0] = v.x; dst[base+1] = v.y;
            dst[base+2] = v.z; dst[base+3] = v.w;
        }
    }

    float m = fmaxf(fmaxf(v.x, v.y), fmaxf(v.z, v.w));
    #pragma unroll
    for (int o=16;o>0;o>>=1) m = fmaxf(m, __shfl_xor_sync(FULL,m,o));
    float s = __expf(v.x-m) + __expf(v.y-m) + __expf(v.z-m) + __expf(v.w-m);
    #pragma unroll
    for (int o=16;o>0;o>>=1) s += __shfl_xor_sync(FULL,s,o);
    float logZ = __logf(s) + m;

    float4 tg = *(const float4*)&targ[base];
    float num = tg.x*(logZ-v.x) + tg.y*(logZ-v.y) + tg.z*(logZ-v.z) + tg.w*(logZ-v.w);
    float den = tg.x + tg.y + tg.z + tg.w;
    #pragma unroll
    for (int o=16;o>0;o>>=1){
        num += __shfl_xor_sync(FULL,num,o);
        den += __shfl_xor_sync(FULL,den,o);
    }
    if (lane == 0 && writeLoss){
        atomicAdd(&g_lnum, (unsigned long long)__double2ll_rn((double)num * FPSCALE));
        atomicAdd(&g_lden, (unsigned long long)__double2ll_rn((double)den * FPSCALE));
    }

    __threadfence();
    __syncthreads();
    __shared__ unsigned s_rank;
    if (tid == 0) s_rank = atomicAdd(&g_ctr, 1u);
    __syncthreads();
    if (s_rank == CBLK-1 && tid == 0){
        if (writeLoss){
            double n = (double)(long long)g_lnum;
            double d = (double)(long long)g_lden;
            out[0] = (float)(n / d);
            g_lnum = 0ull; g_lden = 0ull;
        }
        g_ctr = 0;
    }
}

// ---------------------------------------------------------------------------
extern "C" void kernel_launch(void* const* d_in, const int* in_sizes, int n_in,
                              void* d_out, int out_size){
    const float*         seq  = (const float*)d_in[0];
    const int*           att  = (const int*)d_in[1];
    const unsigned char* ng   = (const unsigned char*)d_in[2];
    const float*         targ = (const float*)d_in[3];
    const float*         Wp   = (const float*)d_in[4];
    const float*         bp   = (const float*)d_in[5];
    const float*         Wa   = (const float*)d_in[6];
    const float*         ba   = (const float*)d_in[7];
    const float*         Wout = (const float*)d_in[8];
    float* out = (float*)d_out;

    k_prep<<<PREP_BLOCKS, 256>>>(seq, Wp, Wa, ng);
    k_gemm<<<dim3(NTOT/64, Mm/64), 256>>>(bp, ba);
    k_biaffine<<<1024, 128>>>(Wout);

    int wantLoss   = (out_size != OUTN) ? 1 : 0;
    int wantOut    = (out_size >= OUTN) ? 1 : 0;
    int dstOffset  = (out_size > OUTN) ? 1 : 0;
    float* dst = out + dstOffset;
    k_combine<<<CBLK, 128>>>(targ, att, (const void*)ng, dst, out,
                             wantOut, dstOffset ? 0 : 1, wantLoss);
}

// round 15
// speedup vs baseline: 1.1166x; 1.1166x over previous
#include <cuda_runtime.h>
#include <cuda_bf16.h>
#include <cuda_fp16.h>
#include <math.h>

#define Bb 2
#define Ss 128
#define Hh 768
#define Cc 5
#define NEGV (-1024.0f)
#define Mm (Bb*Ss)          // 256
#define NTOT (Hh + Cc*Hh)   // 4608
#define NROWS (Bb*Ss*Cc)    // 1280
#define OUTN (Bb*Ss*Cc*Ss)  // 163840

#define KG  (Hh/16)         // 48
#define MI  (Mm/16)         // 16
#define NI8 (NTOT/8)        // 576

#define SEG 8
#define HSEG (Hh/SEG)       // 96
#define JP2 (HSEG/2)        // 48 half2 per segment
#define HH2 (Hh/2)          // 384

__device__ __half g_hp_h[Mm*Hh];
__device__ __half g_ha_h[Mm*Cc*Hh];
__device__ float g_part[SEG*OUTN];
__device__ int   g_ngMode;
__device__ unsigned long long g_lnum;   // fixed-point CE numerator (2^-32)
__device__ unsigned long long g_lden;   // fixed-point CE denominator
__device__ unsigned g_Afh[KG*MI*32*4];
__device__ unsigned g_Afl[KG*MI*32*4];
__device__ unsigned g_Bfh[KG*NI8*32*2];
__device__ unsigned g_Bfl[KG*NI8*32*2];

__device__ __forceinline__ unsigned pack2(__nv_bfloat16 lo, __nv_bfloat16 hi){
    __nv_bfloat162 v; v.x = lo; v.y = hi;
    return *reinterpret_cast<unsigned*>(&v);
}
__device__ __forceinline__ void split_bf(float x, __nv_bfloat16& h, __nv_bfloat16& l){
    h = __float2bfloat16(x);
    l = __float2bfloat16(x - __bfloat162float(h));
}

// ---------------------------------------------------------------------------
// prep: coalesced loads, scattered bf16 hi/lo fragment stores (proven R13).
// LAST BLOCK does ng dtype detection.
// ---------------------------------------------------------------------------
#define AW2 (Mm*HH2)         // 98304 threads (A, float2 each)
#define BW2 (NTOT*HH2)       // 1769472 threads (B)
#define FRAGTOT (AW2+BW2)
#define PREP_BLOCKS (FRAGTOT/256 + 1)

__global__ __launch_bounds__(256) void k_prep(const float* __restrict__ X,
        const float* __restrict__ Wp, const float* __restrict__ Wa,
        const unsigned char* __restrict__ ng){
    if (blockIdx.x == PREP_BLOCKS-1){
        __shared__ int s_b1, s_f3;
        if (threadIdx.x == 0){ s_b1 = 0; s_f3 = 0; }
        __syncthreads();
        int b1 = 0, f3 = 0;
        for (int i = threadIdx.x; i < 16384; i += 256){
            unsigned char v = ng[i];
            int o = i & 3;
            if (o == 1 && v) b1 = 1;
            if (o == 3 && v == 0x3F) f3 = 1;
        }
        if (b1) s_b1 = 1;
        if (f3) s_f3 = 1;
        __syncthreads();
        if (threadIdx.x == 0) g_ngMode = s_b1 ? 0 : (s_f3 ? 2 : 1);
        return;
    }
    int idx = blockIdx.x*256 + threadIdx.x;
    if (idx < AW2){
        int m = idx / HH2, k2 = idx % HH2;
        int k = 2*k2;
        float2 v = *(const float2*)&X[m*Hh + k];
        int mi = m >> 4, g = k >> 4;
        int ml = m & 15, kl = k & 15;
        int reg  = (ml >> 3) | ((kl >> 3) << 1);
        int lane = ((m & 7) << 2) | ((kl >> 1) & 3);
        int w = ((g*MI + mi)*32 + lane)*4 + reg;
        __nv_bfloat16 hx,lx,hy,ly;
        split_bf(v.x, hx, lx); split_bf(v.y, hy, ly);
        g_Afh[w] = pack2(hx, hy);
        g_Afl[w] = pack2(lx, ly);
    } else {
        int t = idx - AW2;
        int n = t / HH2, k2 = t % HH2;
        int k = 2*k2;
        float2 v = (n < Hh) ? *(const float2*)&Wp[n*Hh + k]
                            : *(const float2*)&Wa[(n-Hh)*Hh + k];
        int ni = n >> 3, g = k >> 4;
        int kl = k & 15;
        int reg  = kl >> 3;
        int lane = ((n & 7) << 2) | ((kl >> 1) & 3);
        int w = ((g*NI8 + ni)*32 + lane)*2 + reg;
        __nv_bfloat16 hx,lx,hy,ly;
        split_bf(v.x, hx, lx); split_bf(v.y, hy, ly);
        g_Bfh[w] = pack2(hx, hy);
        g_Bfl[w] = pack2(lx, ly);
    }
}

// ---------------------------------------------------------------------------
// GEMM: mma m16n8k16 bf16, acc += Ah*Bh + Ah*Bl + Al*Bh, double-buffered.
// CTA tile 64(M) x 64(N), 8 warps = 2(M) x 4(N), warp tile 32x16. grid (72,4).
// ---------------------------------------------------------------------------
__device__ __forceinline__ void mma_bf16(float& d0, float& d1, float& d2, float& d3,
        unsigned a0, unsigned a1, unsigned a2, unsigned a3,
        unsigned b0, unsigned b1){
    asm volatile("mma.sync.aligned.m16n8k16.row.col.f32.bf16.bf16.f32 "
        "{%0,%1,%2,%3}, {%4,%5,%6,%7}, {%8,%9}, {%0,%1,%2,%3};"
        : "+f"(d0), "+f"(d1), "+f"(d2), "+f"(d3)
        : "r"(a0), "r"(a1), "r"(a2), "r"(a3), "r"(b0), "r"(b1));
}

__global__ __launch_bounds__(256) void k_gemm(const float* __restrict__ bp,
                                              const float* __restrict__ ba){
    int tid = threadIdx.x;
    int wid = tid >> 5, lane = tid & 31;
    int wr = wid >> 2, wc = wid & 3;
    int mi0 = blockIdx.y*4 + wr*2;
    int ni0 = blockIdx.x*8 + wc*2;

    float acc[2][2][4];
    #pragma unroll
    for (int i=0;i<2;i++) for (int j=0;j<2;j++) for (int q=0;q<4;q++) acc[i][j][q]=0.f;

    const uint4* pAh = reinterpret_cast<const uint4*>(g_Afh);
    const uint4* pAl = reinterpret_cast<const uint4*>(g_Afl);
    const uint2* pBh = reinterpret_cast<const uint2*>(g_Bfh);
    const uint2* pBl = reinterpret_cast<const uint2*>(g_Bfl);

    uint4 Ah[2], Al[2]; uint2 Bh[2], Bl[2];
    #pragma unroll
    for (int mf=0; mf<2; mf++){
        int t = (0*MI + mi0+mf)*32 + lane;
        Ah[mf] = pAh[t]; Al[mf] = pAl[t];
    }
    #pragma unroll
    for (int nf=0; nf<2; nf++){
        int t = (0*NI8 + ni0+nf)*32 + lane;
        Bh[nf] = pBh[t]; Bl[nf] = pBl[t];
    }

    for (int g = 0; g < KG; g++){
        uint4 An[2], Aln[2]; uint2 Bn[2], Bln[2];
        if (g+1 < KG){
            #pragma unroll
            for (int mf=0; mf<2; mf++){
                int t = ((g+1)*MI + mi0+mf)*32 + lane;
                An[mf] = pAh[t]; Aln[mf] = pAl[t];
            }
            #pragma unroll
            for (int nf=0; nf<2; nf++){
                int t = ((g+1)*NI8 + ni0+nf)*32 + lane;
                Bn[nf] = pBh[t]; Bln[nf] = pBl[t];
            }
        }
        #pragma unroll
        for (int mf=0; mf<2; mf++)
            #pragma unroll
            for (int nf=0; nf<2; nf++){
                mma_bf16(acc[mf][nf][0], acc[mf][nf][1], acc[mf][nf][2], acc[mf][nf][3],
                         Ah[mf].x, Ah[mf].y, Ah[mf].z, Ah[mf].w, Bh[nf].x, Bh[nf].y);
                mma_bf16(acc[mf][nf][0], acc[mf][nf][1], acc[mf][nf][2], acc[mf][nf][3],
                         Ah[mf].x, Ah[mf].y, Ah[mf].z, Ah[mf].w, Bl[nf].x, Bl[nf].y);
                mma_bf16(acc[mf][nf][0], acc[mf][nf][1], acc[mf][nf][2], acc[mf][nf][3],
                         Al[mf].x, Al[mf].y, Al[mf].z, Al[mf].w, Bh[nf].x, Bh[nf].y);
            }
        if (g+1 < KG){
            #pragma unroll
            for (int mf=0; mf<2; mf++){ Ah[mf]=An[mf]; Al[mf]=Aln[mf]; }
            #pragma unroll
            for (int nf=0; nf<2; nf++){ Bh[nf]=Bn[nf]; Bl[nf]=Bln[nf]; }
        }
    }

    int r = lane >> 2, c2 = (lane & 3)*2;
    #pragma unroll
    for (int nf=0; nf<2; nf++){
        int n = (ni0+nf)*8 + c2;
        float2 bias = (n < Hh) ? *(const float2*)&bp[n] : *(const float2*)&ba[n-Hh];
        #pragma unroll
        for (int mf=0; mf<2; mf++){
            int m1 = (mi0+mf)*16 + r;
            int m2 = m1 + 8;
            __half2 v1 = __floats2half2_rn(acc[mf][nf][0] + bias.x, acc[mf][nf][1] + bias.y);
            __half2 v2 = __floats2half2_rn(acc[mf][nf][2] + bias.x, acc[mf][nf][3] + bias.y);
            if (n < Hh){
                *(__half2*)&g_hp_h[m1*Hh + n] = v1;
                *(__half2*)&g_hp_h[m2*Hh + n] = v2;
            } else {
                *(__half2*)&g_ha_h[m1*(Cc*Hh) + (n-Hh)] = v1;
                *(__half2*)&g_ha_h[m2*(Cc*Hh) + (n-Hh)] = v2;
            }
        }
    }
}

// ---------------------------------------------------------------------------
// biaffine partial (proven): all-f16x2, 8-way h-split, tile 32p x 8a,
// 128 threads, padded s_ha. grid 1024.
// ---------------------------------------------------------------------------
__global__ __launch_bounds__(128,8) void k_biaffine(const float* __restrict__ Wout){
    __shared__ __half2 s_hp[32][JP2+1];
    __shared__ __half2 s_ha[Cc][JP2][9];
    __shared__ __half2 s_w[Cc][JP2];
    int bx = blockIdx.x;
    int seg  = bx & 7;
    int rest = bx >> 3;
    int b   = rest >> 6;
    int rem = rest & 63;
    int p0 = (rem >> 4) * 32;
    int a0 = (rem & 15) * 8;
    int tid = threadIdx.x;
    int p = tid >> 3, a = tid & 7;
    int jbase = seg * JP2;

    const __half2* HP = reinterpret_cast<const __half2*>(g_hp_h);
    const __half2* HA = reinterpret_cast<const __half2*>(g_ha_h);

    #pragma unroll
    for (int i = 0; i < 12; i++){
        int idx = tid + i*128;
        int r = idx / JP2, jp = idx % JP2;
        s_hp[r][jp] = HP[(b*Ss + p0 + r)*HH2 + jbase + jp];
    }
    #pragma unroll
    for (int i = 0; i < 15; i++){
        int idx = tid + i*128;
        int al = idx / (Cc*JP2);
        int rr = idx % (Cc*JP2);
        int c = rr / JP2, jp = rr % JP2;
        s_ha[c][jp][al] = HA[((b*Ss + a0 + al)*Cc + c)*HH2 + jbase + jp];
    }
    for (int idx = tid; idx < Cc*JP2; idx += 128){
        int c = idx / JP2, jp = idx % JP2;
        float2 v = *(const float2*)&Wout[c*Hh + seg*HSEG + 2*jp];
        s_w[c][jp] = __floats2half2_rn(v.x, v.y);
    }
    __syncthreads();

    float fA[Cc] = {}, fB[Cc] = {};
    #pragma unroll 1
    for (int blk = 0; blk < 4; blk++){
        __half2 accA[Cc], accB[Cc];
        #pragma unroll
        for (int c=0;c<Cc;c++){
            accA[c] = __floats2half2_rn(0.f, 0.f);
            accB[c] = __floats2half2_rn(0.f, 0.f);
        }
        #pragma unroll
        for (int j=0;j<12;j++){
            int jp = blk*12 + j;
            __half2 hpA = s_hp[p][jp];
            __half2 hpB = s_hp[p+16][jp];
            #pragma unroll
            for (int c=0;c<Cc;c++){
                __half2 ha = s_ha[c][jp][a];
                __half2 w  = s_w[c][jp];
                __half2 xA = __hadd2(hpA, ha);
                __half2 xB = __hadd2(hpB, ha);
                unsigned tA, tB;
                asm("tanh.approx.f16x2 %0, %1;" : "=r"(tA) : "r"(*(unsigned*)&xA));
                asm("tanh.approx.f16x2 %0, %1;" : "=r"(tB) : "r"(*(unsigned*)&xB));
                accA[c] = __hfma2(*(__half2*)&tA, w, accA[c]);
                accB[c] = __hfma2(*(__half2*)&tB, w, accB[c]);
            }
        }
        #pragma unroll
        for (int c=0;c<Cc;c++){
            float2 vA = __half22float2(accA[c]);
            float2 vB = __half22float2(accB[c]);
            fA[c] += vA.x + vA.y;
            fB[c] += vB.x + vB.y;
        }
    }
    int pgA = p0 + p, pgB = p0 + p + 16, ag = a0 + a;
    #pragma unroll
    for (int c=0;c<Cc;c++){
        g_part[seg*OUTN + ((b*Ss+pgA)*Cc + c)*Ss + ag] = fA[c];
        g_part[seg*OUTN + ((b*Ss+pgB)*Cc + c)*Ss + ag] = fB[c];
    }
}

// ---------------------------------------------------------------------------
// combine: warp-per-row, vectorized; int64 fixed-point CE atomics.
// NO finalize tail — fence/counter removed; k_final does the divide.
// ---------------------------------------------------------------------------
#define CBLK (NROWS/4)   // 320
#define FPSCALE 4294967296.0

__global__ __launch_bounds__(128) void k_combine(const float* __restrict__ targ,
        const int* __restrict__ att, const void* __restrict__ ng,
        float* __restrict__ dst,
        int writeOut, int dstAligned, int writeLoss){
    const unsigned FULL = 0xffffffffu;
    int tid = threadIdx.x;
    int w = tid >> 5, lane = tid & 31;
    int row = blockIdx.x*4 + w;
    int bp = row / Cc;
    int b = bp >> 7;
    int base = row*Ss + lane*4;

    float4 v = make_float4(0.f,0.f,0.f,0.f);
    #pragma unroll
    for (int k=0;k<SEG;k++){
        float4 t = *(const float4*)&g_part[k*OUTN + base];
        v.x += t.x; v.y += t.y; v.z += t.z; v.w += t.w;
    }

    int mode = g_ngMode;
    bool m0=false, m1=false, m2=false, m3=false;
    if (mode == 1){
        #pragma unroll
        for (int c=0;c<Cc;c++){
            int4 q = *(const int4*)&((const int*)ng)[(bp*Cc + c)*Ss + lane*4];
            m0 |= q.x!=0; m1 |= q.y!=0; m2 |= q.z!=0; m3 |= q.w!=0;
        }
    } else if (mode == 2){
        #pragma unroll
        for (int c=0;c<Cc;c++){
            float4 q = *(const float4*)&((const float*)ng)[(bp*Cc + c)*Ss + lane*4];
            m0 |= q.x!=0.f; m1 |= q.y!=0.f; m2 |= q.z!=0.f; m3 |= q.w!=0.f;
        }
    } else {
        #pragma unroll
        for (int c=0;c<Cc;c++){
            uchar4 q = *(const uchar4*)&((const unsigned char*)ng)[(bp*Cc + c)*Ss + lane*4];
            m0 |= q.x!=0; m1 |= q.y!=0; m2 |= q.z!=0; m3 |= q.w!=0;
        }
    }
    int4 av = *(const int4*)&att[b*Ss + lane*4];
    v.x += (m0 && av.x>0) ? 0.f : NEGV;
    v.y += (m1 && av.y>0) ? 0.f : NEGV;
    v.z += (m2 && av.z>0) ? 0.f : NEGV;
    v.w += (m3 && av.w>0) ? 0.f : NEGV;
    if (writeOut){
        if (dstAligned){
            *(float4*)&dst[base] = v;
        } else {
            dst[base+0] = v.x; dst[base+1] = v.y;
            dst[base+2] = v.z; dst[base+3] = v.w;
        }
    }

    float m = fmaxf(fmaxf(v.x, v.y), fmaxf(v.z, v.w));
    #pragma unroll
    for (int o=16;o>0;o>>=1) m = fmaxf(m, __shfl_xor_sync(FULL,m,o));
    float s = __expf(v.x-m) + __expf(v.y-m) + __expf(v.z-m) + __expf(v.w-m);
    #pragma unroll
    for (int o=16;o>0;o>>=1) s += __shfl_xor_sync(FULL,s,o);
    float logZ = __logf(s) + m;

    float4 tg = *(const float4*)&targ[base];
    float num = tg.x*(logZ-v.x) + tg.y*(logZ-v.y) + tg.z*(logZ-v.z) + tg.w*(logZ-v.w);
    float den = tg.x + tg.y + tg.z + tg.w;
    #pragma unroll
    for (int o=16;o>0;o>>=1){
        num += __shfl_xor_sync(FULL,num,o);
        den += __shfl_xor_sync(FULL,den,o);
    }
    if (lane == 0 && writeLoss){
        atomicAdd(&g_lnum, (unsigned long long)__double2ll_rn((double)num * FPSCALE));
        atomicAdd(&g_lden, (unsigned long long)__double2ll_rn((double)den * FPSCALE));
    }
}

// final: divide + reset (kernel boundary orders the atomics)
__global__ void k_final(float* __restrict__ out){
    double n = (double)(long long)g_lnum;
    double d = (double)(long long)g_lden;
    out[0] = (float)(n / d);
    g_lnum = 0ull; g_lden = 0ull;
}

// ---------------------------------------------------------------------------
extern "C" void kernel_launch(void* const* d_in, const int* in_sizes, int n_in,
                              void* d_out, int out_size){
    const float*         seq  = (const float*)d_in[0];
    const int*           att  = (const int*)d_in[1];
    const unsigned char* ng   = (const unsigned char*)d_in[2];
    const float*         targ = (const float*)d_in[3];
    const float*         Wp   = (const float*)d_in[4];
    const float*         bp   = (const float*)d_in[5];
    const float*         Wa   = (const float*)d_in[6];
    const float*         ba   = (const float*)d_in[7];
    const float*         Wout = (const float*)d_in[8];
    float* out = (float*)d_out;

    k_prep<<<PREP_BLOCKS, 256>>>(seq, Wp, Wa, ng);
    k_gemm<<<dim3(NTOT/64, Mm/64), 256>>>(bp, ba);
    k_biaffine<<<1024, 128>>>(Wout);

    int wantLoss   = (out_size != OUTN) ? 1 : 0;
    int wantOut    = (out_size >= OUTN) ? 1 : 0;
    int dstOffset  = (out_size > OUTN) ? 1 : 0;
    float* dst = out + dstOffset;
    k_combine<<<CBLK, 128>>>(targ, att, (const void*)ng, dst,
                             wantOut, dstOffset ? 0 : 1, wantLoss);
    if (wantLoss)
        k_final<<<1, 1>>>(out);
}

// round 16
// speedup vs baseline: 1.1462x; 1.0265x over previous
#include <cuda_runtime.h>
#include <cuda_bf16.h>
#include <cuda_fp16.h>
#include <math.h>

#define Bb 2
#define Ss 128
#define Hh 768
#define Cc 5
#define NEGV (-1024.0f)
#define Mm (Bb*Ss)          // 256
#define NTOT (Hh + Cc*Hh)   // 4608
#define NROWS (Bb*Ss*Cc)    // 1280
#define OUTN (Bb*Ss*Cc*Ss)  // 163840

#define KG  (Hh/16)         // 48
#define MI  (Mm/16)         // 16
#define NI8 (NTOT/8)        // 576

#define SEG 8
#define HSEG (Hh/SEG)       // 96
#define JP2 (HSEG/2)        // 48 half2 per segment
#define HH2 (Hh/2)          // 384

__device__ __half g_hp_h[Mm*Hh];
__device__ __half g_ha_h[Mm*Cc*Hh];
__device__ float g_part[SEG*OUTN];
__device__ int   g_ngMode;
__device__ unsigned g_ctr;
__device__ unsigned long long g_lnum;   // fixed-point CE numerator (2^-32)
__device__ unsigned long long g_lden;   // fixed-point CE denominator
__device__ unsigned g_Afh[KG*MI*32*4];
__device__ unsigned g_Afl[KG*MI*32*4];
__device__ unsigned g_Bfh[KG*NI8*32*2];
__device__ unsigned g_Bfl[KG*NI8*32*2];

__device__ __forceinline__ unsigned pack2(__nv_bfloat16 lo, __nv_bfloat16 hi){
    __nv_bfloat162 v; v.x = lo; v.y = hi;
    return *reinterpret_cast<unsigned*>(&v);
}
__device__ __forceinline__ void split_bf(float x, __nv_bfloat16& h, __nv_bfloat16& l){
    h = __float2bfloat16(x);
    l = __float2bfloat16(x - __bfloat162float(h));
}

// ---------------------------------------------------------------------------
// prep: w-indexed (coalesced fragment stores, cached scattered loads) —
// the R12-measured-faster layout. LAST BLOCK does ng dtype detection.
//   A word w: reg=w&3, lane=(w>>2)&31, tile=w>>7: mi=tile%MI, g=tile/MI
//     m = mi*16 + (lane>>2) + (reg&1)*8 ; k = g*16 + (lane&3)*2 + (reg>>1)*8
//   B word w: reg=w&1, lane=(w>>1)&31, tile=w>>6: ni=tile%NI8, g=tile/NI8
//     n = ni*8 + (lane>>2)            ; k = g*16 + (lane&3)*2 + reg*8
// ---------------------------------------------------------------------------
#define AW (KG*MI*32*4)      // 98304
#define BW (KG*NI8*32*2)     // 1769472
#define FRAGTOT (AW+BW)
#define PREP_BLOCKS (FRAGTOT/256 + 1)

__global__ __launch_bounds__(256) void k_prep(const float* __restrict__ X,
        const float* __restrict__ Wp, const float* __restrict__ Wa,
        const unsigned char* __restrict__ ng){
    if (blockIdx.x == PREP_BLOCKS-1){
        __shared__ int s_b1, s_f3;
        if (threadIdx.x == 0){ s_b1 = 0; s_f3 = 0; }
        __syncthreads();
        int b1 = 0, f3 = 0;
        for (int i = threadIdx.x; i < 16384; i += 256){
            unsigned char v = ng[i];
            int o = i & 3;
            if (o == 1 && v) b1 = 1;
            if (o == 3 && v == 0x3F) f3 = 1;
        }
        if (b1) s_b1 = 1;
        if (f3) s_f3 = 1;
        __syncthreads();
        if (threadIdx.x == 0) g_ngMode = s_b1 ? 0 : (s_f3 ? 2 : 1);
        return;
    }
    int idx = blockIdx.x*256 + threadIdx.x;
    if (idx < AW){
        int w = idx;
        int reg = w & 3, lane = (w>>2)&31;
        int tile = w>>7;
        int mi = tile % MI, g = tile / MI;
        int m = mi*16 + (lane>>2) + (reg&1)*8;
        int k = g*16 + (lane&3)*2 + (reg>>1)*8;
        float2 v = *(const float2*)&X[m*Hh + k];
        __nv_bfloat16 hx,lx,hy,ly;
        split_bf(v.x, hx, lx); split_bf(v.y, hy, ly);
        g_Afh[w] = pack2(hx, hy);
        g_Afl[w] = pack2(lx, ly);
    } else {
        int w = idx - AW;
        int reg = w & 1, lane = (w>>1)&31;
        int tile = w>>6;
        int ni = tile % NI8, g = tile / NI8;
        int n = ni*8 + (lane>>2);
        int k = g*16 + (lane&3)*2 + reg*8;
        float2 v = (n < Hh) ? *(const float2*)&Wp[n*Hh + k]
                            : *(const float2*)&Wa[(n-Hh)*Hh + k];
        __nv_bfloat16 hx,lx,hy,ly;
        split_bf(v.x, hx, lx); split_bf(v.y, hy, ly);
        g_Bfh[w] = pack2(hx, hy);
        g_Bfl[w] = pack2(lx, ly);
    }
}

// ---------------------------------------------------------------------------
// GEMM: mma m16n8k16 bf16, acc += Ah*Bh + Ah*Bl + Al*Bh, double-buffered.
// CTA tile 64(M) x 64(N), 8 warps = 2(M) x 4(N), warp tile 32x16. grid (72,4).
// ---------------------------------------------------------------------------
__device__ __forceinline__ void mma_bf16(float& d0, float& d1, float& d2, float& d3,
        unsigned a0, unsigned a1, unsigned a2, unsigned a3,
        unsigned b0, unsigned b1){
    asm volatile("mma.sync.aligned.m16n8k16.row.col.f32.bf16.bf16.f32 "
        "{%0,%1,%2,%3}, {%4,%5,%6,%7}, {%8,%9}, {%0,%1,%2,%3};"
        : "+f"(d0), "+f"(d1), "+f"(d2), "+f"(d3)
        : "r"(a0), "r"(a1), "r"(a2), "r"(a3), "r"(b0), "r"(b1));
}

__global__ __launch_bounds__(256) void k_gemm(const float* __restrict__ bp,
                                              const float* __restrict__ ba){
    int tid = threadIdx.x;
    int wid = tid >> 5, lane = tid & 31;
    int wr = wid >> 2, wc = wid & 3;
    int mi0 = blockIdx.y*4 + wr*2;
    int ni0 = blockIdx.x*8 + wc*2;

    float acc[2][2][4];
    #pragma unroll
    for (int i=0;i<2;i++) for (int j=0;j<2;j++) for (int q=0;q<4;q++) acc[i][j][q]=0.f;

    const uint4* pAh = reinterpret_cast<const uint4*>(g_Afh);
    const uint4* pAl = reinterpret_cast<const uint4*>(g_Afl);
    const uint2* pBh = reinterpret_cast<const uint2*>(g_Bfh);
    const uint2* pBl = reinterpret_cast<const uint2*>(g_Bfl);

    uint4 Ah[2], Al[2]; uint2 Bh[2], Bl[2];
    #pragma unroll
    for (int mf=0; mf<2; mf++){
        int t = (0*MI + mi0+mf)*32 + lane;
        Ah[mf] = pAh[t]; Al[mf] = pAl[t];
    }
    #pragma unroll
    for (int nf=0; nf<2; nf++){
        int t = (0*NI8 + ni0+nf)*32 + lane;
        Bh[nf] = pBh[t]; Bl[nf] = pBl[t];
    }

    for (int g = 0; g < KG; g++){
        uint4 An[2], Aln[2]; uint2 Bn[2], Bln[2];
        if (g+1 < KG){
            #pragma unroll
            for (int mf=0; mf<2; mf++){
                int t = ((g+1)*MI + mi0+mf)*32 + lane;
                An[mf] = pAh[t]; Aln[mf] = pAl[t];
            }
            #pragma unroll
            for (int nf=0; nf<2; nf++){
                int t = ((g+1)*NI8 + ni0+nf)*32 + lane;
                Bn[nf] = pBh[t]; Bln[nf] = pBl[t];
            }
        }
        #pragma unroll
        for (int mf=0; mf<2; mf++)
            #pragma unroll
            for (int nf=0; nf<2; nf++){
                mma_bf16(acc[mf][nf][0], acc[mf][nf][1], acc[mf][nf][2], acc[mf][nf][3],
                         Ah[mf].x, Ah[mf].y, Ah[mf].z, Ah[mf].w, Bh[nf].x, Bh[nf].y);
                mma_bf16(acc[mf][nf][0], acc[mf][nf][1], acc[mf][nf][2], acc[mf][nf][3],
                         Ah[mf].x, Ah[mf].y, Ah[mf].z, Ah[mf].w, Bl[nf].x, Bl[nf].y);
                mma_bf16(acc[mf][nf][0], acc[mf][nf][1], acc[mf][nf][2], acc[mf][nf][3],
                         Al[mf].x, Al[mf].y, Al[mf].z, Al[mf].w, Bh[nf].x, Bh[nf].y);
            }
        if (g+1 < KG){
            #pragma unroll
            for (int mf=0; mf<2; mf++){ Ah[mf]=An[mf]; Al[mf]=Aln[mf]; }
            #pragma unroll
            for (int nf=0; nf<2; nf++){ Bh[nf]=Bn[nf]; Bl[nf]=Bln[nf]; }
        }
    }

    int r = lane >> 2, c2 = (lane & 3)*2;
    #pragma unroll
    for (int nf=0; nf<2; nf++){
        int n = (ni0+nf)*8 + c2;
        float2 bias = (n < Hh) ? *(const float2*)&bp[n] : *(const float2*)&ba[n-Hh];
        #pragma unroll
        for (int mf=0; mf<2; mf++){
            int m1 = (mi0+mf)*16 + r;
            int m2 = m1 + 8;
            __half2 v1 = __floats2half2_rn(acc[mf][nf][0] + bias.x, acc[mf][nf][1] + bias.y);
            __half2 v2 = __floats2half2_rn(acc[mf][nf][2] + bias.x, acc[mf][nf][3] + bias.y);
            if (n < Hh){
                *(__half2*)&g_hp_h[m1*Hh + n] = v1;
                *(__half2*)&g_hp_h[m2*Hh + n] = v2;
            } else {
                *(__half2*)&g_ha_h[m1*(Cc*Hh) + (n-Hh)] = v1;
                *(__half2*)&g_ha_h[m2*(Cc*Hh) + (n-Hh)] = v2;
            }
        }
    }
}

// ---------------------------------------------------------------------------
// biaffine partial (proven): all-f16x2, 8-way h-split, tile 32p x 8a,
// 128 threads, padded s_ha. grid 1024.
// ---------------------------------------------------------------------------
__global__ __launch_bounds__(128,8) void k_biaffine(const float* __restrict__ Wout){
    __shared__ __half2 s_hp[32][JP2+1];
    __shared__ __half2 s_ha[Cc][JP2][9];
    __shared__ __half2 s_w[Cc][JP2];
    int bx = blockIdx.x;
    int seg  = bx & 7;
    int rest = bx >> 3;
    int b   = rest >> 6;
    int rem = rest & 63;
    int p0 = (rem >> 4) * 32;
    int a0 = (rem & 15) * 8;
    int tid = threadIdx.x;
    int p = tid >> 3, a = tid & 7;
    int jbase = seg * JP2;

    const __half2* HP = reinterpret_cast<const __half2*>(g_hp_h);
    const __half2* HA = reinterpret_cast<const __half2*>(g_ha_h);

    #pragma unroll
    for (int i = 0; i < 12; i++){
        int idx = tid + i*128;
        int r = idx / JP2, jp = idx % JP2;
        s_hp[r][jp] = HP[(b*Ss + p0 + r)*HH2 + jbase + jp];
    }
    #pragma unroll
    for (int i = 0; i < 15; i++){
        int idx = tid + i*128;
        int al = idx / (Cc*JP2);
        int rr = idx % (Cc*JP2);
        int c = rr / JP2, jp = rr % JP2;
        s_ha[c][jp][al] = HA[((b*Ss + a0 + al)*Cc + c)*HH2 + jbase + jp];
    }
    for (int idx = tid; idx < Cc*JP2; idx += 128){
        int c = idx / JP2, jp = idx % JP2;
        float2 v = *(const float2*)&Wout[c*Hh + seg*HSEG + 2*jp];
        s_w[c][jp] = __floats2half2_rn(v.x, v.y);
    }
    __syncthreads();

    float fA[Cc] = {}, fB[Cc] = {};
    #pragma unroll 1
    for (int blk = 0; blk < 4; blk++){
        __half2 accA[Cc], accB[Cc];
        #pragma unroll
        for (int c=0;c<Cc;c++){
            accA[c] = __floats2half2_rn(0.f, 0.f);
            accB[c] = __floats2half2_rn(0.f, 0.f);
        }
        #pragma unroll
        for (int j=0;j<12;j++){
            int jp = blk*12 + j;
            __half2 hpA = s_hp[p][jp];
            __half2 hpB = s_hp[p+16][jp];
            #pragma unroll
            for (int c=0;c<Cc;c++){
                __half2 ha = s_ha[c][jp][a];
                __half2 w  = s_w[c][jp];
                __half2 xA = __hadd2(hpA, ha);
                __half2 xB = __hadd2(hpB, ha);
                unsigned tA, tB;
                asm("tanh.approx.f16x2 %0, %1;" : "=r"(tA) : "r"(*(unsigned*)&xA));
                asm("tanh.approx.f16x2 %0, %1;" : "=r"(tB) : "r"(*(unsigned*)&xB));
                accA[c] = __hfma2(*(__half2*)&tA, w, accA[c]);
                accB[c] = __hfma2(*(__half2*)&tB, w, accB[c]);
            }
        }
        #pragma unroll
        for (int c=0;c<Cc;c++){
            float2 vA = __half22float2(accA[c]);
            float2 vB = __half22float2(accB[c]);
            fA[c] += vA.x + vA.y;
            fB[c] += vB.x + vB.y;
        }
    }
    int pgA = p0 + p, pgB = p0 + p + 16, ag = a0 + a;
    #pragma unroll
    for (int c=0;c<Cc;c++){
        g_part[seg*OUTN + ((b*Ss+pgA)*Cc + c)*Ss + ag] = fA[c];
        g_part[seg*OUTN + ((b*Ss+pgB)*Cc + c)*Ss + ag] = fB[c];
    }
}

// ---------------------------------------------------------------------------
// combine: warp-per-row, vectorized; int64 fixed-point CE atomics.
// Finalize in-kernel via acq_rel counter (no fence, no extra launch):
// each row-warp's lane 0 adds lnum/lden (relaxed) then counter (acq_rel).
// The 1280th arriver sees all prior adds (release->acquire chain),
// divides, writes out[0], resets.
// ---------------------------------------------------------------------------
#define CBLK (NROWS/4)   // 320
#define FPSCALE 4294967296.0

__global__ __launch_bounds__(128) void k_combine(const float* __restrict__ targ,
        const int* __restrict__ att, const void* __restrict__ ng,
        float* __restrict__ dst, float* __restrict__ out,
        int writeOut, int dstAligned, int writeLoss){
    const unsigned FULL = 0xffffffffu;
    int tid = threadIdx.x;
    int w = tid >> 5, lane = tid & 31;
    int row = blockIdx.x*4 + w;
    int bp = row / Cc;
    int b = bp >> 7;
    int base = row*Ss + lane*4;

    float4 v = make_float4(0.f,0.f,0.f,0.f);
    #pragma unroll
    for (int k=0;k<SEG;k++){
        float4 t = *(const float4*)&g_part[k*OUTN + base];
        v.x += t.x; v.y += t.y; v.z += t.z; v.w += t.w;
    }

    int mode = g_ngMode;
    bool m0=false, m1=false, m2=false, m3=false;
    if (mode == 1){
        #pragma unroll
        for (int c=0;c<Cc;c++){
            int4 q = *(const int4*)&((const int*)ng)[(bp*Cc + c)*Ss + lane*4];
            m0 |= q.x!=0; m1 |= q.y!=0; m2 |= q.z!=0; m3 |= q.w!=0;
        }
    } else if (mode == 2){
        #pragma unroll
        for (int c=0;c<Cc;c++){
            float4 q = *(const float4*)&((const float*)ng)[(bp*Cc + c)*Ss + lane*4];
            m0 |= q.x!=0.f; m1 |= q.y!=0.f; m2 |= q.z!=0.f; m3 |= q.w!=0.f;
        }
    } else {
        #pragma unroll
        for (int c=0;c<Cc;c++){
            uchar4 q = *(const uchar4*)&((const unsigned char*)ng)[(bp*Cc + c)*Ss + lane*4];
            m0 |= q.x!=0; m1 |= q.y!=0; m2 |= q.z!=0; m3 |= q.w!=0;
        }
    }
    int4 av = *(const int4*)&att[b*Ss + lane*4];
    v.x += (m0 && av.x>0) ? 0.f : NEGV;
    v.y += (m1 && av.y>0) ? 0.f : NEGV;
    v.z += (m2 && av.z>0) ? 0.f : NEGV;
    v.w += (m3 && av.w>0) ? 0.f : NEGV;
    if (writeOut){
        if (dstAligned){
            *(float4*)&dst[base] = v;
        } else {
            dst[base+0] = v.x; dst[base+1] = v.y;
            dst[base+2] = v.z; dst[base+3] = v.w;
        }
    }

    float m = fmaxf(fmaxf(v.x, v.y), fmaxf(v.z, v.w));
    #pragma unroll
    for (int o=16;o>0;o>>=1) m = fmaxf(m, __shfl_xor_sync(FULL,m,o));
    float s = __expf(v.x-m) + __expf(v.y-m) + __expf(v.z-m) + __expf(v.w-m);
    #pragma unroll
    for (int o=16;o>0;o>>=1) s += __shfl_xor_sync(FULL,s,o);
    float logZ = __logf(s) + m;

    float4 tg = *(const float4*)&targ[base];
    float num = tg.x*(logZ-v.x) + tg.y*(logZ-v.y) + tg.z*(logZ-v.z) + tg.w*(logZ-v.w);
    float den = tg.x + tg.y + tg.z + tg.w;
    #pragma unroll
    for (int o=16;o>0;o>>=1){
        num += __shfl_xor_sync(FULL,num,o);
        den += __shfl_xor_sync(FULL,den,o);
    }
    if (lane == 0 && writeLoss){
        atomicAdd(&g_lnum, (unsigned long long)__double2ll_rn((double)num * FPSCALE));
        atomicAdd(&g_lden, (unsigned long long)__double2ll_rn((double)den * FPSCALE));
        unsigned old;
        asm volatile("atom.acq_rel.gpu.add.u32 %0, [%1], 1;"
                     : "=r"(old) : "l"(&g_ctr) : "memory");
        if (old == NROWS-1){
            unsigned long long n = atomicAdd(&g_lnum, 0ull);
            unsigned long long d = atomicAdd(&g_lden, 0ull);
            out[0] = (float)((double)(long long)n / (double)(long long)d);
            atomicExch(&g_lnum, 0ull);
            atomicExch(&g_lden, 0ull);
            atomicExch(&g_ctr, 0u);
        }
    }
}

// ---------------------------------------------------------------------------
extern "C" void kernel_launch(void* const* d_in, const int* in_sizes, int n_in,
                              void* d_out, int out_size){
    const float*         seq  = (const float*)d_in[0];
    const int*           att  = (const int*)d_in[1];
    const unsigned char* ng   = (const unsigned char*)d_in[2];
    const float*         targ = (const float*)d_in[3];
    const float*         Wp   = (const float*)d_in[4];
    const float*         bp   = (const float*)d_in[5];
    const float*         Wa   = (const float*)d_in[6];
    const float*         ba   = (const float*)d_in[7];
    const float*         Wout = (const float*)d_in[8];
    float* out = (float*)d_out;

    k_prep<<<PREP_BLOCKS, 256>>>(seq, Wp, Wa, ng);
    k_gemm<<<dim3(NTOT/64, Mm/64), 256>>>(bp, ba);
    k_biaffine<<<1024, 128>>>(Wout);

    int wantLoss   = (out_size != OUTN) ? 1 : 0;
    int wantOut    = (out_size >= OUTN) ? 1 : 0;
    int dstOffset  = (out_size > OUTN) ? 1 : 0;
    float* dst = out + dstOffset;
    k_combine<<<CBLK, 128>>>(targ, att, (const void*)ng, dst, out,
                             wantOut, dstOffset ? 0 : 1, wantLoss);
}